// round 9
// baseline (speedup 1.0000x reference)
#include <cuda_runtime.h>
#include <cuda_fp16.h>
#include <cstdint>
#include <math.h>

#define T_TOK 6304
#define DMODEL 768
#define NEXP 16
#define TM 128
#define TN 128
#define KSTEP 64                     // halfs per stage (128 B rows)
#define NSTAGE (DMODEL / KSTEP)      // 12
#define MAX_TILES 128

#define SLOT_B 16384                 // bytes per stage slot: 128 rows x 128 B
#define RING_OFF 2048
#define SMEM_BYTES (RING_OFF + 6 * SLOT_B)   // 100352: bias + 3-slot A ring + 3-slot B ring
#define STG_STRIDE 136               // epilogue staging row stride (floats), 64 rows per pass

// ---------------- scratch (device globals; no allocations allowed) ----------
__device__ __half g_xh[T_TOK * DMODEL];
__device__ __half g_w1h[NEXP * DMODEL * DMODEL];
__device__ __half g_w2h[NEXP * DMODEL * DMODEL];
__device__ __half g_hidden[T_TOK * DMODEL];
__device__ int    g_idx[T_TOK];
__device__ int    g_counts[NEXP];
__device__ int    g_off[NEXP + 1];
__device__ int    g_cursor[NEXP];
__device__ int    g_perm[T_TOK];
__device__ int    g_tile_e[MAX_TILES];
__device__ int    g_tile_row[MAX_TILES];

// ---------------- helpers ----------------------------------------------------
__device__ __forceinline__ void ldsm4(uint32_t* r, uint32_t addr) {
    asm volatile("ldmatrix.sync.aligned.m8n8.x4.shared.b16 {%0,%1,%2,%3}, [%4];"
                 : "=r"(r[0]), "=r"(r[1]), "=r"(r[2]), "=r"(r[3]) : "r"(addr));
}
__device__ __forceinline__ void mma_f16(float* c, const uint32_t* a, const uint32_t* b) {
    asm volatile(
        "mma.sync.aligned.m16n8k16.row.col.f32.f16.f16.f32 "
        "{%0,%1,%2,%3}, {%4,%5,%6,%7}, {%8,%9}, {%0,%1,%2,%3};"
        : "+f"(c[0]), "+f"(c[1]), "+f"(c[2]), "+f"(c[3])
        : "r"(a[0]), "r"(a[1]), "r"(a[2]), "r"(a[3]), "r"(b[0]), "r"(b[1]));
}
__device__ __forceinline__ void cpa16(uint32_t dst, const void* src, int srcsize) {
    asm volatile("cp.async.cg.shared.global [%0], [%1], 16, %2;"
                 :: "r"(dst), "l"(src), "r"(srcsize) : "memory");
}
#define CP_COMMIT() asm volatile("cp.async.commit_group;" ::: "memory")
#define CP_WAIT1()  asm volatile("cp.async.wait_group 1;" ::: "memory")
#define CP_WAIT0()  asm volatile("cp.async.wait_group 0;" ::: "memory")

// swizzled byte offset of 16B chunk (row, c) inside a 128x64-half slot (128 B rows)
__device__ __forceinline__ uint32_t swz_off(int row, int c) {
    return (uint32_t)(row * 128 + ((c ^ (row & 7)) << 4));
}

// ---------------- merged weight convert (+ counts zeroing) -------------------
__global__ void cvtw_kernel(const float* __restrict__ W1, const float* __restrict__ W2,
                            __half* __restrict__ w1h, __half* __restrict__ w2h, int n8) {
    int i = blockIdx.x * blockDim.x + threadIdx.x;
    if (blockIdx.x == 0 && threadIdx.x < NEXP) g_counts[threadIdx.x] = 0;
    const float* src; __half* dst; int j;
    if (i < n8)            { src = W1; dst = w1h; j = i; }
    else if (i < 2 * n8)   { src = W2; dst = w2h; j = i - n8; }
    else return;
    const float4* s = (const float4*)src + 2 * (size_t)j;
    float4 a = s[0], b = s[1];
    __half2 h0 = __floats2half2_rn(a.x, a.y), h1 = __floats2half2_rn(a.z, a.w);
    __half2 h2 = __floats2half2_rn(b.x, b.y), h3 = __floats2half2_rn(b.z, b.w);
    ((uint4*)dst)[j] = make_uint4(*(uint32_t*)&h0, *(uint32_t*)&h1,
                                  *(uint32_t*)&h2, *(uint32_t*)&h3);
}

// ---------------- gate: logits/argmax/counts + x -> fp16 ---------------------
// 788 blocks x 8 tokens (exact). Row cached in 24 regs, reused across 16 experts.
__global__ void gate_kernel(const float* __restrict__ x,
                            const float* __restrict__ Wg,
                            const float* __restrict__ bg) {
    __shared__ float wgs[NEXP * DMODEL];
    int tid = threadIdx.x;
    for (int i = tid; i < NEXP * DMODEL; i += 256) wgs[i] = Wg[i];
    __syncthreads();

    int w = tid >> 5, l = tid & 31;
    int t = blockIdx.x * 8 + w;
    {
        const float* xr = x + (size_t)t * DMODEL;
        float xv[24];
        #pragma unroll
        for (int j = 0; j < 24; j++) xv[j] = xr[l + 32 * j];
        float best = -1e30f; int bi = 0;
        #pragma unroll 1
        for (int e = 0; e < NEXP; e++) {
            float s = 0.f;
            const float* wr = wgs + e * DMODEL + l;
            #pragma unroll
            for (int j = 0; j < 24; j++) s += xv[j] * wr[32 * j];
            #pragma unroll
            for (int o = 16; o; o >>= 1) s += __shfl_xor_sync(0xffffffffu, s, o);
            s += bg[e];
            if (s > best) { best = s; bi = e; }   // strict > : first max (jnp.argmax)
        }
        if (l == 0) { g_idx[t] = bi; atomicAdd(&g_counts[bi], 1); }
    }
    // fp16 copy of this block's 8 rows: 768 half8-chunks, 3 per thread
    size_t base = (size_t)blockIdx.x * 8 * DMODEL / 8;   // in half8 units
    #pragma unroll
    for (int j = 0; j < 3; j++) {
        size_t idx = base + tid + 256 * j;
        const float4* s = (const float4*)x + 2 * idx;
        float4 a = s[0], b = s[1];
        __half2 h0 = __floats2half2_rn(a.x, a.y), h1 = __floats2half2_rn(a.z, a.w);
        __half2 h2 = __floats2half2_rn(b.x, b.y), h3 = __floats2half2_rn(b.z, b.w);
        ((uint4*)g_xh)[idx] = make_uint4(*(uint32_t*)&h0, *(uint32_t*)&h1,
                                         *(uint32_t*)&h2, *(uint32_t*)&h3);
    }
}

__global__ void scan_kernel() {
    if (threadIdx.x != 0) return;
    int off = 0, nt = 0;
    for (int e = 0; e < NEXP; e++) {
        g_off[e] = off;
        g_cursor[e] = off;
        int c = g_counts[e];
        for (int r = 0; r < c; r += TM) { g_tile_e[nt] = e; g_tile_row[nt] = off + r; nt++; }
        off += c;
    }
    g_off[NEXP] = off;
    for (; nt < MAX_TILES; nt++) g_tile_e[nt] = -1;
}

__global__ void scatter_kernel() {
    int t = blockIdx.x * 256 + threadIdx.x;
    if (t >= T_TOK) return;
    int p = atomicAdd(&g_cursor[g_idx[t]], 1);
    g_perm[p] = t;
}

// ---------------- fp16 mma.sync grouped GEMM, cp.async 3-slot ring, K=64 -----
// PHASE 1: hidden[r,:] = fp16(GELU(xh[perm[r]] @ W1h[e]^T + b1[e]))
// PHASE 2: out[perm[r],:] = hidden[r] @ W2h[e]^T + b2[e]
template <int PHASE>
__global__ void __launch_bounds__(256, 2)
mlp_mma(const __half* __restrict__ Ax, const __half* __restrict__ W,
        const float* __restrict__ bias, float* __restrict__ out)
{
    int tile = blockIdx.x;
    int e = g_tile_e[tile];
    if (e < 0) return;
    int row0 = g_tile_row[tile];
    int rend = g_off[e + 1];
    int n0 = blockIdx.y * TN;

    extern __shared__ char sm[];
    float* bias_s = (float*)sm;
    char* ring = sm + RING_OFF;
    uint32_t ring_s = (uint32_t)__cvta_generic_to_shared(ring);
    float* stg = (float*)ring;                 // epilogue staging alias (64 x 136 fp32)

    int tid = threadIdx.x;
    int wid = tid >> 5, lane = tid & 31;
    int wr = wid & 3, wc = wid >> 2;           // warp tile: rows wr*32, cols wc*64
    int lrow = lane >> 2, lcol = lane & 3;
    int lq = lane >> 3, lr = lane & 7;
    int a_row = wr * 32 + (lq & 1) * 8 + lr;   // + mm*16
    int a_cb  = lq >> 1;                       // + kk*2
    int b_row = wc * 64 + (lq >> 1) * 8 + lr;  // + np*16
    int b_cb  = lq & 1;                        // + kk*2

    if (tid < TN) bias_s[tid] = bias[(size_t)e * DMODEL + n0 + tid];

    // loader: 2 threads per tile row; each thread 4 A + 4 B 16B chunks per stage
    int side = tid & 1, rowp = tid >> 1;
    const __half* asrc; int asz;
    const __half* bsrc;
    uint32_t doff[4];
    {
        int ar = row0 + rowp;
        bool v = ar < rend;
        int srow;
        if (PHASE == 1) srow = v ? g_perm[ar] : 0;
        else            srow = v ? ar : 0;
        asrc = Ax + (size_t)srow * DMODEL + side * 32;
        asz = v ? 16 : 0;
        bsrc = W + (size_t)e * DMODEL * DMODEL + (size_t)(n0 + rowp) * DMODEL + side * 32;
        #pragma unroll
        for (int q = 0; q < 4; q++) doff[q] = swz_off(rowp, side * 4 + q);
    }

    float acc[2][8][4];
    #pragma unroll
    for (int mm = 0; mm < 2; mm++)
        #pragma unroll
        for (int nn = 0; nn < 8; nn++)
            #pragma unroll
            for (int j = 0; j < 4; j++) acc[mm][nn][j] = 0.f;

    // prologue: stages 0,1 in flight
    #pragma unroll
    for (int s = 0; s < 2; s++) {
        uint32_t aslot = ring_s + s * SLOT_B;
        uint32_t bslot = ring_s + 3 * SLOT_B + s * SLOT_B;
        int ko = s * KSTEP;
        #pragma unroll
        for (int q = 0; q < 4; q++) {
            cpa16(aslot + doff[q], asrc + ko + q * 8, asz);
            cpa16(bslot + doff[q], bsrc + ko + q * 8, 16);
        }
        CP_COMMIT();
    }

    // mainloop: compute s from slot s%3; prefetch s+2 into slot (s+2)%3
    int slot = 0;
    #pragma unroll 1
    for (int s = 0; s < NSTAGE; s++) {
        CP_WAIT1();
        __syncthreads();
        if (s + 2 < NSTAGE) {
            int sn = slot + 2; if (sn >= 3) sn -= 3;
            uint32_t aslot = ring_s + sn * SLOT_B;
            uint32_t bslot = ring_s + 3 * SLOT_B + sn * SLOT_B;
            int ko = (s + 2) * KSTEP;
            #pragma unroll
            for (int q = 0; q < 4; q++) {
                cpa16(aslot + doff[q], asrc + ko + q * 8, asz);
                cpa16(bslot + doff[q], bsrc + ko + q * 8, 16);
            }
        }
        CP_COMMIT();   // commit every iter to keep wait_group accounting uniform

        uint32_t As = ring_s + slot * SLOT_B;
        uint32_t Bs = ring_s + 3 * SLOT_B + slot * SLOT_B;
        #pragma unroll
        for (int kk = 0; kk < 4; kk++) {
            uint32_t af[2][4];
            #pragma unroll
            for (int mm = 0; mm < 2; mm++)
                ldsm4(af[mm], As + swz_off(a_row + mm * 16, a_cb + kk * 2));
            uint32_t bf[4][4];
            #pragma unroll
            for (int np = 0; np < 4; np++)
                ldsm4(bf[np], Bs + swz_off(b_row + np * 16, b_cb + kk * 2));
            #pragma unroll
            for (int np = 0; np < 4; np++) {
                mma_f16(acc[0][2 * np],     af[0], &bf[np][0]);
                mma_f16(acc[1][2 * np],     af[1], &bf[np][0]);
                mma_f16(acc[0][2 * np + 1], af[0], &bf[np][2]);
                mma_f16(acc[1][2 * np + 1], af[1], &bf[np][2]);
            }
        }
        if (++slot == 3) slot = 0;
    }
    CP_WAIT0();
    __syncthreads();

    // ---- epilogue: two passes of 64 rows through fp32 staging ----
    #pragma unroll
    for (int p = 0; p < 2; p++) {
        if ((wr >> 1) == p) {
            int rbase = (wr & 1) * 32;
            #pragma unroll
            for (int mm = 0; mm < 2; mm++) {
                #pragma unroll
                for (int nn = 0; nn < 8; nn++) {
                    int col = wc * 64 + nn * 8 + 2 * lcol;
                    int row = rbase + mm * 16 + lrow;
                    float b0 = bias_s[col], b1 = bias_s[col + 1];
                    float v0 = acc[mm][nn][0] + b0, v1 = acc[mm][nn][1] + b1;
                    float v2 = acc[mm][nn][2] + b0, v3 = acc[mm][nn][3] + b1;
                    if (PHASE == 1) {
                        v0 = 0.5f * v0 * (1.0f + erff(v0 * 0.70710678118654752f));
                        v1 = 0.5f * v1 * (1.0f + erff(v1 * 0.70710678118654752f));
                        v2 = 0.5f * v2 * (1.0f + erff(v2 * 0.70710678118654752f));
                        v3 = 0.5f * v3 * (1.0f + erff(v3 * 0.70710678118654752f));
                    }
                    *(float2*)(stg + row * STG_STRIDE + col) = make_float2(v0, v1);
                    *(float2*)(stg + (row + 8) * STG_STRIDE + col) = make_float2(v2, v3);
                }
            }
        }
        __syncthreads();
        {
            int rloc = tid >> 2, q = tid & 3;
            int gr = row0 + p * 64 + rloc;
            if (gr < rend) {
                const float* srow = stg + rloc * STG_STRIDE + q * 32;
                if (PHASE == 1) {
                    __half* dst = g_hidden + (size_t)gr * DMODEL + n0 + q * 32;
                    #pragma unroll
                    for (int j = 0; j < 4; j++) {
                        float4 aa = ((const float4*)srow)[2 * j];
                        float4 bb = ((const float4*)srow)[2 * j + 1];
                        __half2 h0 = __floats2half2_rn(aa.x, aa.y);
                        __half2 h1 = __floats2half2_rn(aa.z, aa.w);
                        __half2 h2 = __floats2half2_rn(bb.x, bb.y);
                        __half2 h3 = __floats2half2_rn(bb.z, bb.w);
                        ((uint4*)dst)[j] = make_uint4(*(uint32_t*)&h0, *(uint32_t*)&h1,
                                                      *(uint32_t*)&h2, *(uint32_t*)&h3);
                    }
                } else {
                    float* dst = out + (size_t)g_perm[gr] * DMODEL + n0 + q * 32;
                    #pragma unroll
                    for (int j = 0; j < 8; j++)
                        ((float4*)dst)[j] = ((const float4*)srow)[j];
                }
            }
        }
        __syncthreads();
    }
}

// ---------------- launch -----------------------------------------------------
extern "C" void kernel_launch(void* const* d_in, const int* in_sizes, int n_in,
                              void* d_out, int out_size) {
    const float* x  = (const float*)d_in[0];
    const float* W1 = (const float*)d_in[1];
    const float* b1 = (const float*)d_in[2];
    const float* W2 = (const float*)d_in[3];
    const float* b2 = (const float*)d_in[4];
    const float* Wg = (const float*)d_in[5];
    const float* bg = (const float*)d_in[6];
    float* out = (float*)d_out;

    cudaFuncSetAttribute(mlp_mma<1>, cudaFuncAttributeMaxDynamicSharedMemorySize, SMEM_BYTES);
    cudaFuncSetAttribute(mlp_mma<2>, cudaFuncAttributeMaxDynamicSharedMemorySize, SMEM_BYTES);

    __half *xh_p, *w1h_p, *w2h_p, *hid_p;
    cudaGetSymbolAddress((void**)&xh_p, g_xh);
    cudaGetSymbolAddress((void**)&w1h_p, g_w1h);
    cudaGetSymbolAddress((void**)&w2h_p, g_w2h);
    cudaGetSymbolAddress((void**)&hid_p, g_hidden);

    int nW8 = NEXP * DMODEL * DMODEL / 8;          // 1,179,648
    cvtw_kernel<<<(2 * nW8 + 255) / 256, 256>>>(W1, W2, w1h_p, w2h_p, nW8);
    gate_kernel<<<T_TOK / 8, 256>>>(x, Wg, bg);
    scan_kernel<<<1, 1>>>();
    scatter_kernel<<<(T_TOK + 255) / 256, 256>>>();

    dim3 g(MAX_TILES, DMODEL / TN);
    mlp_mma<1><<<g, 256, SMEM_BYTES>>>(xh_p, w1h_p, b1, nullptr);
    mlp_mma<2><<<g, 256, SMEM_BYTES>>>(hid_p, w2h_p, b2, out);
}

// round 11
// speedup vs baseline: 1.4994x; 1.4994x over previous
#include <cuda_runtime.h>
#include <cuda_fp16.h>
#include <cstdint>
#include <math.h>

#define T_TOK 6304
#define DMODEL 768
#define NEXP 16
#define TM 128
#define TN 128
#define KSTEP 32                     // halfs per stage
#define NSTAGE (DMODEL / KSTEP)      // 24
#define MAX_TILES 128

#define SLOT_B 8192                  // bytes per A (or B) stage slot: 128 rows x 64B
#define RING_OFF 2048
#define SMEM_BYTES (RING_OFF + 8 * SLOT_B)   // 67584: bias + 4-stage A ring + 4-stage B ring
#define STG_STRIDE 136               // epilogue staging row stride (floats), 64 rows per pass

// ---------------- scratch (device globals; no allocations allowed) ----------
__device__ __half g_xh[T_TOK * DMODEL];
__device__ __half g_w1h[NEXP * DMODEL * DMODEL];
__device__ __half g_w2h[NEXP * DMODEL * DMODEL];
__device__ __half g_hidden[T_TOK * DMODEL];
__device__ int    g_idx[T_TOK];
__device__ int    g_counts[NEXP];
__device__ int    g_off[NEXP + 1];
__device__ int    g_cursor[NEXP];
__device__ int    g_perm[T_TOK];
__device__ int    g_tile_e[MAX_TILES];
__device__ int    g_tile_row[MAX_TILES];

// ---------------- helpers ----------------------------------------------------
__device__ __forceinline__ void ldsm4(uint32_t* r, uint32_t addr) {
    asm volatile("ldmatrix.sync.aligned.m8n8.x4.shared.b16 {%0,%1,%2,%3}, [%4];"
                 : "=r"(r[0]), "=r"(r[1]), "=r"(r[2]), "=r"(r[3]) : "r"(addr));
}
__device__ __forceinline__ void mma_f16(float* c, const uint32_t* a, const uint32_t* b) {
    asm volatile(
        "mma.sync.aligned.m16n8k16.row.col.f32.f16.f16.f32 "
        "{%0,%1,%2,%3}, {%4,%5,%6,%7}, {%8,%9}, {%0,%1,%2,%3};"
        : "+f"(c[0]), "+f"(c[1]), "+f"(c[2]), "+f"(c[3])
        : "r"(a[0]), "r"(a[1]), "r"(a[2]), "r"(a[3]), "r"(b[0]), "r"(b[1]));
}
__device__ __forceinline__ void cpa16(uint32_t dst, const void* src, int srcsize) {
    asm volatile("cp.async.cg.shared.global [%0], [%1], 16, %2;"
                 :: "r"(dst), "l"(src), "r"(srcsize) : "memory");
}
#define CP_COMMIT() asm volatile("cp.async.commit_group;" ::: "memory")
#define CP_WAIT2()  asm volatile("cp.async.wait_group 2;" ::: "memory")
#define CP_WAIT0()  asm volatile("cp.async.wait_group 0;" ::: "memory")

// swizzled byte offset of 16B chunk (row, c) inside a 128x32-half tile slot
__device__ __forceinline__ uint32_t swz_off(int row, int c) {
    return (uint32_t)(row * 64 + ((c ^ ((row >> 1) & 3)) << 4));
}

// ---------------- merged weight convert (+ counts zeroing) -------------------
__global__ void cvtw_kernel(const float* __restrict__ W1, const float* __restrict__ W2,
                            __half* __restrict__ w1h, __half* __restrict__ w2h, int n8) {
    int i = blockIdx.x * blockDim.x + threadIdx.x;
    if (blockIdx.x == 0 && threadIdx.x < NEXP) g_counts[threadIdx.x] = 0;
    const float* src; __half* dst; int j;
    if (i < n8)            { src = W1; dst = w1h; j = i; }
    else if (i < 2 * n8)   { src = W2; dst = w2h; j = i - n8; }
    else return;
    const float4* s = (const float4*)src + 2 * (size_t)j;
    float4 a = s[0], b = s[1];
    __half2 h0 = __floats2half2_rn(a.x, a.y), h1 = __floats2half2_rn(a.z, a.w);
    __half2 h2 = __floats2half2_rn(b.x, b.y), h3 = __floats2half2_rn(b.z, b.w);
    ((uint4*)dst)[j] = make_uint4(*(uint32_t*)&h0, *(uint32_t*)&h1,
                                  *(uint32_t*)&h2, *(uint32_t*)&h3);
}

// ---------------- gate: logits/argmax/counts + x -> fp16 ---------------------
// 788 blocks x 8 tokens (exact). Row cached in 24 regs, reused across 16 experts.
__global__ void gate_kernel(const float* __restrict__ x,
                            const float* __restrict__ Wg,
                            const float* __restrict__ bg) {
    __shared__ float wgs[NEXP * DMODEL];
    int tid = threadIdx.x;
    for (int i = tid; i < NEXP * DMODEL; i += 256) wgs[i] = Wg[i];
    __syncthreads();

    int w = tid >> 5, l = tid & 31;
    int t = blockIdx.x * 8 + w;
    {
        const float* xr = x + (size_t)t * DMODEL;
        float xv[24];
        #pragma unroll
        for (int j = 0; j < 24; j++) xv[j] = xr[l + 32 * j];
        float best = -1e30f; int bi = 0;
        #pragma unroll 1
        for (int e = 0; e < NEXP; e++) {
            float s = 0.f;
            const float* wr = wgs + e * DMODEL + l;
            #pragma unroll
            for (int j = 0; j < 24; j++) s += xv[j] * wr[32 * j];
            #pragma unroll
            for (int o = 16; o; o >>= 1) s += __shfl_xor_sync(0xffffffffu, s, o);
            s += bg[e];
            if (s > best) { best = s; bi = e; }   // strict > : first max (jnp.argmax)
        }
        if (l == 0) { g_idx[t] = bi; atomicAdd(&g_counts[bi], 1); }
    }
    // fp16 copy of this block's 8 rows: 768 half8-chunks, 3 per thread
    size_t base = (size_t)blockIdx.x * 8 * DMODEL / 8;   // in half8 units
    #pragma unroll
    for (int j = 0; j < 3; j++) {
        size_t idx = base + tid + 256 * j;
        const float4* s = (const float4*)x + 2 * idx;
        float4 a = s[0], b = s[1];
        __half2 h0 = __floats2half2_rn(a.x, a.y), h1 = __floats2half2_rn(a.z, a.w);
        __half2 h2 = __floats2half2_rn(b.x, b.y), h3 = __floats2half2_rn(b.z, b.w);
        ((uint4*)g_xh)[idx] = make_uint4(*(uint32_t*)&h0, *(uint32_t*)&h1,
                                         *(uint32_t*)&h2, *(uint32_t*)&h3);
    }
}

__global__ void scan_kernel() {
    if (threadIdx.x != 0) return;
    int off = 0, nt = 0;
    for (int e = 0; e < NEXP; e++) {
        g_off[e] = off;
        g_cursor[e] = off;
        int c = g_counts[e];
        for (int r = 0; r < c; r += TM) { g_tile_e[nt] = e; g_tile_row[nt] = off + r; nt++; }
        off += c;
    }
    g_off[NEXP] = off;
    for (; nt < MAX_TILES; nt++) g_tile_e[nt] = -1;
}

__global__ void scatter_kernel() {
    int t = blockIdx.x * 256 + threadIdx.x;
    if (t >= T_TOK) return;
    int p = atomicAdd(&g_cursor[g_idx[t]], 1);
    g_perm[p] = t;
}

// ---------------- fp16 mma.sync grouped GEMM, cp.async 4-stage ring ----------
// PHASE 1: hidden[r,:] = fp16(GELU(xh[perm[r]] @ W1h[e]^T + b1[e]))
// PHASE 2: out[perm[r],:] = hidden[r] @ W2h[e]^T + b2[e]
template <int PHASE>
__global__ void __launch_bounds__(256, 2)
mlp_mma(const __half* __restrict__ Ax, const __half* __restrict__ W,
        const float* __restrict__ bias, float* __restrict__ out)
{
    int tile = blockIdx.x;
    int e = g_tile_e[tile];
    if (e < 0) return;
    int row0 = g_tile_row[tile];
    int rend = g_off[e + 1];
    int n0 = blockIdx.y * TN;

    extern __shared__ char sm[];
    float* bias_s = (float*)sm;
    char* ring = sm + RING_OFF;
    uint32_t ring_s = (uint32_t)__cvta_generic_to_shared(ring);
    float* stg = (float*)ring;                 // epilogue staging alias (64 x 136 fp32)

    int tid = threadIdx.x;
    int wid = tid >> 5, lane = tid & 31;
    int wr = wid & 3, wc = wid >> 2;           // warp tile: rows wr*32, cols wc*64
    int lrow = lane >> 2, lcol = lane & 3;
    int lq = lane >> 3, lr = lane & 7;
    int a_row = wr * 32 + (lq & 1) * 8 + lr;   // + mm*16
    int a_cb  = lq >> 1;                       // chunk base, + kk*2
    int b_row = wc * 64 + (lq >> 1) * 8 + lr;  // + np*16
    int b_cb  = lq & 1;

    if (tid < TN) bias_s[tid] = bias[(size_t)e * DMODEL + n0 + tid];

    // loader mapping: thread -> 2 A chunks + 2 B chunks per stage
    // chunk c = tid&3 (16B = 8 halfs), rows tid>>2 and tid>>2 + 64
    int c = tid & 3;
    int r0 = tid >> 2, r1 = r0 + 64;
    const __half* asrc[2]; int asz[2];
    const __half* bsrc[2];
    uint32_t doff[2];
    {
        int rr[2] = {r0, r1};
        #pragma unroll
        for (int j = 0; j < 2; j++) {
            int ar = row0 + rr[j];
            bool v = ar < rend;
            int srow;
            if (PHASE == 1) srow = v ? g_perm[ar] : 0;
            else            srow = v ? ar : 0;
            asrc[j] = Ax + (size_t)srow * DMODEL + c * 8;
            asz[j] = v ? 16 : 0;
            bsrc[j] = W + (size_t)e * DMODEL * DMODEL + (size_t)(n0 + rr[j]) * DMODEL + c * 8;
            doff[j] = swz_off(rr[j], c);
        }
    }

    float acc[2][8][4];
    #pragma unroll
    for (int mm = 0; mm < 2; mm++)
        #pragma unroll
        for (int nn = 0; nn < 8; nn++)
            #pragma unroll
            for (int j = 0; j < 4; j++) acc[mm][nn][j] = 0.f;

    // prologue: stages 0,1,2 in flight
    #pragma unroll
    for (int s = 0; s < 3; s++) {
        uint32_t aslot = ring_s + (s & 3) * SLOT_B;
        uint32_t bslot = ring_s + 4 * SLOT_B + (s & 3) * SLOT_B;
        int ko = s * KSTEP;
        cpa16(aslot + doff[0], asrc[0] + ko, asz[0]);
        cpa16(aslot + doff[1], asrc[1] + ko, asz[1]);
        cpa16(bslot + doff[0], bsrc[0] + ko, 16);
        cpa16(bslot + doff[1], bsrc[1] + ko, 16);
        CP_COMMIT();
    }

    // mainloop
    #pragma unroll 1
    for (int s = 0; s < NSTAGE; s++) {
        CP_WAIT2();
        __syncthreads();
        if (s + 3 < NSTAGE) {
            int sn = s + 3;
            uint32_t aslot = ring_s + (sn & 3) * SLOT_B;
            uint32_t bslot = ring_s + 4 * SLOT_B + (sn & 3) * SLOT_B;
            int ko = sn * KSTEP;
            cpa16(aslot + doff[0], asrc[0] + ko, asz[0]);
            cpa16(aslot + doff[1], asrc[1] + ko, asz[1]);
            cpa16(bslot + doff[0], bsrc[0] + ko, 16);
            cpa16(bslot + doff[1], bsrc[1] + ko, 16);
        }
        CP_COMMIT();   // commit every iter (possibly empty) to keep wait_group math uniform

        uint32_t As = ring_s + (s & 3) * SLOT_B;
        uint32_t Bs = ring_s + 4 * SLOT_B + (s & 3) * SLOT_B;
        #pragma unroll
        for (int kk = 0; kk < 2; kk++) {
            uint32_t af[2][4];
            #pragma unroll
            for (int mm = 0; mm < 2; mm++) {
                int i = a_row + mm * 16;
                ldsm4(af[mm], As + swz_off(i, a_cb + kk * 2));
            }
            uint32_t bf[4][4];
            #pragma unroll
            for (int np = 0; np < 4; np++) {
                int i = b_row + np * 16;
                ldsm4(bf[np], Bs + swz_off(i, b_cb + kk * 2));
            }
            #pragma unroll
            for (int np = 0; np < 4; np++) {
                mma_f16(acc[0][2 * np],     af[0], &bf[np][0]);
                mma_f16(acc[1][2 * np],     af[1], &bf[np][0]);
                mma_f16(acc[0][2 * np + 1], af[0], &bf[np][2]);
                mma_f16(acc[1][2 * np + 1], af[1], &bf[np][2]);
            }
        }
    }
    CP_WAIT0();
    __syncthreads();

    // ---- epilogue: two passes of 64 rows through fp32 staging ----
    #pragma unroll
    for (int p = 0; p < 2; p++) {
        if ((wr >> 1) == p) {
            int rbase = (wr & 1) * 32;
            #pragma unroll
            for (int mm = 0; mm < 2; mm++) {
                #pragma unroll
                for (int nn = 0; nn < 8; nn++) {
                    int col = wc * 64 + nn * 8 + 2 * lcol;
                    int row = rbase + mm * 16 + lrow;
                    float b0 = bias_s[col], b1 = bias_s[col + 1];
                    float v0 = acc[mm][nn][0] + b0, v1 = acc[mm][nn][1] + b1;
                    float v2 = acc[mm][nn][2] + b0, v3 = acc[mm][nn][3] + b1;
                    if (PHASE == 1) {
                        v0 = 0.5f * v0 * (1.0f + erff(v0 * 0.70710678118654752f));
                        v1 = 0.5f * v1 * (1.0f + erff(v1 * 0.70710678118654752f));
                        v2 = 0.5f * v2 * (1.0f + erff(v2 * 0.70710678118654752f));
                        v3 = 0.5f * v3 * (1.0f + erff(v3 * 0.70710678118654752f));
                    }
                    *(float2*)(stg + row * STG_STRIDE + col) = make_float2(v0, v1);
                    *(float2*)(stg + (row + 8) * STG_STRIDE + col) = make_float2(v2, v3);
                }
            }
        }
        __syncthreads();
        // writeout: 4 threads per row, 32 floats each (coalesced)
        {
            int rloc = tid >> 2, q = tid & 3;
            int gr = row0 + p * 64 + rloc;
            if (gr < rend) {
                const float* srow = stg + rloc * STG_STRIDE + q * 32;
                if (PHASE == 1) {
                    __half* dst = g_hidden + (size_t)gr * DMODEL + n0 + q * 32;
                    #pragma unroll
                    for (int j = 0; j < 4; j++) {
                        float4 aa = ((const float4*)srow)[2 * j];
                        float4 bb = ((const float4*)srow)[2 * j + 1];
                        __half2 h0 = __floats2half2_rn(aa.x, aa.y);
                        __half2 h1 = __floats2half2_rn(aa.z, aa.w);
                        __half2 h2 = __floats2half2_rn(bb.x, bb.y);
                        __half2 h3 = __floats2half2_rn(bb.z, bb.w);
                        ((uint4*)dst)[j] = make_uint4(*(uint32_t*)&h0, *(uint32_t*)&h1,
                                                      *(uint32_t*)&h2, *(uint32_t*)&h3);
                    }
                } else {
                    float* dst = out + (size_t)g_perm[gr] * DMODEL + n0 + q * 32;
                    #pragma unroll
                    for (int j = 0; j < 8; j++)
                        ((float4*)dst)[j] = ((const float4*)srow)[j];
                }
            }
        }
        __syncthreads();
    }
}

// ---------------- launch -----------------------------------------------------
extern "C" void kernel_launch(void* const* d_in, const int* in_sizes, int n_in,
                              void* d_out, int out_size) {
    const float* x  = (const float*)d_in[0];
    const float* W1 = (const float*)d_in[1];
    const float* b1 = (const float*)d_in[2];
    const float* W2 = (const float*)d_in[3];
    const float* b2 = (const float*)d_in[4];
    const float* Wg = (const float*)d_in[5];
    const float* bg = (const float*)d_in[6];
    float* out = (float*)d_out;

    cudaFuncSetAttribute(mlp_mma<1>, cudaFuncAttributeMaxDynamicSharedMemorySize, SMEM_BYTES);
    cudaFuncSetAttribute(mlp_mma<2>, cudaFuncAttributeMaxDynamicSharedMemorySize, SMEM_BYTES);

    __half *xh_p, *w1h_p, *w2h_p, *hid_p;
    cudaGetSymbolAddress((void**)&xh_p, g_xh);
    cudaGetSymbolAddress((void**)&w1h_p, g_w1h);
    cudaGetSymbolAddress((void**)&w2h_p, g_w2h);
    cudaGetSymbolAddress((void**)&hid_p, g_hidden);

    int nW8 = NEXP * DMODEL * DMODEL / 8;          // 1,179,648
    cvtw_kernel<<<(2 * nW8 + 255) / 256, 256>>>(W1, W2, w1h_p, w2h_p, nW8);
    gate_kernel<<<T_TOK / 8, 256>>>(x, Wg, bg);
    scan_kernel<<<1, 1>>>();
    scatter_kernel<<<(T_TOK + 255) / 256, 256>>>();

    dim3 g(MAX_TILES, DMODEL / TN);
    mlp_mma<1><<<g, 256, SMEM_BYTES>>>(xh_p, w1h_p, b1, nullptr);
    mlp_mma<2><<<g, 256, SMEM_BYTES>>>(hid_p, w2h_p, b2, out);
}

// round 12
// speedup vs baseline: 1.8234x; 1.2161x over previous
#include <cuda_runtime.h>
#include <cuda_fp16.h>
#include <cstdint>
#include <math.h>

#define T_TOK 6304
#define DMODEL 768
#define NEXP 16
#define TM 128
#define TN 64
#define KSTEP 32                     // halfs per stage
#define NSTAGE (DMODEL / KSTEP)      // 24
#define MAX_TILES 128

#define SLOT_A 8192                  // A stage slot: 128 rows x 64 B
#define SLOT_BB 4096                 // B stage slot: 64 rows x 64 B
#define RING_OFF 2048
#define SMEM_BYTES (RING_OFF + 4 * SLOT_A + 4 * SLOT_BB)   // 51200
#define STG_STRIDE 68                // epilogue staging row stride (floats)

// ---------------- scratch (device globals; no allocations allowed) ----------
__device__ __half g_xh[T_TOK * DMODEL];
__device__ __half g_w1h[NEXP * DMODEL * DMODEL];
__device__ __half g_w2h[NEXP * DMODEL * DMODEL];
__device__ __half g_hidden[T_TOK * DMODEL];
__device__ int    g_idx[T_TOK];
__device__ int    g_counts[NEXP];
__device__ int    g_off[NEXP + 1];
__device__ int    g_cursor[NEXP];
__device__ int    g_perm[T_TOK];
__device__ int    g_tile_e[MAX_TILES];
__device__ int    g_tile_row[MAX_TILES];

// ---------------- helpers ----------------------------------------------------
__device__ __forceinline__ void ldsm4(uint32_t* r, uint32_t addr) {
    asm volatile("ldmatrix.sync.aligned.m8n8.x4.shared.b16 {%0,%1,%2,%3}, [%4];"
                 : "=r"(r[0]), "=r"(r[1]), "=r"(r[2]), "=r"(r[3]) : "r"(addr));
}
__device__ __forceinline__ void mma_f16(float* c, const uint32_t* a, const uint32_t* b) {
    asm volatile(
        "mma.sync.aligned.m16n8k16.row.col.f32.f16.f16.f32 "
        "{%0,%1,%2,%3}, {%4,%5,%6,%7}, {%8,%9}, {%0,%1,%2,%3};"
        : "+f"(c[0]), "+f"(c[1]), "+f"(c[2]), "+f"(c[3])
        : "r"(a[0]), "r"(a[1]), "r"(a[2]), "r"(a[3]), "r"(b[0]), "r"(b[1]));
}
__device__ __forceinline__ void cpa16(uint32_t dst, const void* src, int srcsize) {
    asm volatile("cp.async.cg.shared.global [%0], [%1], 16, %2;"
                 :: "r"(dst), "l"(src), "r"(srcsize) : "memory");
}
#define CP_COMMIT() asm volatile("cp.async.commit_group;" ::: "memory")
#define CP_WAIT2()  asm volatile("cp.async.wait_group 2;" ::: "memory")
#define CP_WAIT0()  asm volatile("cp.async.wait_group 0;" ::: "memory")

// swizzled byte offset of 16B chunk (row, c) inside a 64B-per-row tile slot
__device__ __forceinline__ uint32_t swz_off(int row, int c) {
    return (uint32_t)(row * 64 + ((c ^ ((row >> 1) & 3)) << 4));
}

// ---------------- merged weight convert (+ counts zeroing) -------------------
__global__ void cvtw_kernel(const float* __restrict__ W1, const float* __restrict__ W2,
                            __half* __restrict__ w1h, __half* __restrict__ w2h, int n8) {
    int i = blockIdx.x * blockDim.x + threadIdx.x;
    if (blockIdx.x == 0 && threadIdx.x < NEXP) g_counts[threadIdx.x] = 0;
    const float* src; __half* dst; int j;
    if (i < n8)            { src = W1; dst = w1h; j = i; }
    else if (i < 2 * n8)   { src = W2; dst = w2h; j = i - n8; }
    else return;
    const float4* s = (const float4*)src + 2 * (size_t)j;
    float4 a = s[0], b = s[1];
    __half2 h0 = __floats2half2_rn(a.x, a.y), h1 = __floats2half2_rn(a.z, a.w);
    __half2 h2 = __floats2half2_rn(b.x, b.y), h3 = __floats2half2_rn(b.z, b.w);
    ((uint4*)dst)[j] = make_uint4(*(uint32_t*)&h0, *(uint32_t*)&h1,
                                  *(uint32_t*)&h2, *(uint32_t*)&h3);
}

// ---------------- gate: logits/argmax/counts + x -> fp16 ---------------------
__global__ void gate_kernel(const float* __restrict__ x,
                            const float* __restrict__ Wg,
                            const float* __restrict__ bg) {
    __shared__ float wgs[NEXP * DMODEL];
    int tid = threadIdx.x;
    for (int i = tid; i < NEXP * DMODEL; i += 256) wgs[i] = Wg[i];
    __syncthreads();

    int w = tid >> 5, l = tid & 31;
    int t = blockIdx.x * 8 + w;
    {
        const float* xr = x + (size_t)t * DMODEL;
        float xv[24];
        #pragma unroll
        for (int j = 0; j < 24; j++) xv[j] = xr[l + 32 * j];
        float best = -1e30f; int bi = 0;
        #pragma unroll 1
        for (int e = 0; e < NEXP; e++) {
            float s = 0.f;
            const float* wr = wgs + e * DMODEL + l;
            #pragma unroll
            for (int j = 0; j < 24; j++) s += xv[j] * wr[32 * j];
            #pragma unroll
            for (int o = 16; o; o >>= 1) s += __shfl_xor_sync(0xffffffffu, s, o);
            s += bg[e];
            if (s > best) { best = s; bi = e; }   // strict > : first max (jnp.argmax)
        }
        if (l == 0) { g_idx[t] = bi; atomicAdd(&g_counts[bi], 1); }
    }
    size_t base = (size_t)blockIdx.x * 8 * DMODEL / 8;
    #pragma unroll
    for (int j = 0; j < 3; j++) {
        size_t idx = base + tid + 256 * j;
        const float4* s = (const float4*)x + 2 * idx;
        float4 a = s[0], b = s[1];
        __half2 h0 = __floats2half2_rn(a.x, a.y), h1 = __floats2half2_rn(a.z, a.w);
        __half2 h2 = __floats2half2_rn(b.x, b.y), h3 = __floats2half2_rn(b.z, b.w);
        ((uint4*)g_xh)[idx] = make_uint4(*(uint32_t*)&h0, *(uint32_t*)&h1,
                                         *(uint32_t*)&h2, *(uint32_t*)&h3);
    }
}

__global__ void scan_kernel() {
    if (threadIdx.x != 0) return;
    int off = 0, nt = 0;
    for (int e = 0; e < NEXP; e++) {
        g_off[e] = off;
        g_cursor[e] = off;
        int c = g_counts[e];
        for (int r = 0; r < c; r += TM) { g_tile_e[nt] = e; g_tile_row[nt] = off + r; nt++; }
        off += c;
    }
    g_off[NEXP] = off;
    for (; nt < MAX_TILES; nt++) g_tile_e[nt] = -1;
}

__global__ void scatter_kernel() {
    int t = blockIdx.x * 256 + threadIdx.x;
    if (t >= T_TOK) return;
    int p = atomicAdd(&g_cursor[g_idx[t]], 1);
    g_perm[p] = t;
}

// ---------------- fp16 mma.sync grouped GEMM, 128x64 tiles -------------------
// PHASE 1: hidden[r,:] = fp16(GELU(xh[perm[r]] @ W1h[e]^T + b1[e]))
// PHASE 2: out[perm[r],:] = hidden[r] @ W2h[e]^T + b2[e]
template <int PHASE>
__global__ void __launch_bounds__(256, 3)
mlp_mma(const __half* __restrict__ Ax, const __half* __restrict__ W,
        const float* __restrict__ bias, float* __restrict__ out)
{
    int tile = blockIdx.x;
    int e = g_tile_e[tile];
    if (e < 0) return;
    int row0 = g_tile_row[tile];
    int rend = g_off[e + 1];
    int n0 = blockIdx.y * TN;

    extern __shared__ char sm[];
    float* bias_s = (float*)sm;
    char* ring = sm + RING_OFF;
    uint32_t ring_s = (uint32_t)__cvta_generic_to_shared(ring);
    float* stg = (float*)ring;                 // epilogue staging alias (128 x 68 fp32)

    int tid = threadIdx.x;
    int wid = tid >> 5, lane = tid & 31;
    int wr = wid & 3, wc = wid >> 2;           // warp tile: rows wr*32, cols wc*32
    int lrow = lane >> 2, lcol = lane & 3;
    int lq = lane >> 3, lr = lane & 7;
    int a_row = wr * 32 + (lq & 1) * 8 + lr;   // + mm*16
    int a_cb  = lq >> 1;                       // + kk*2
    int b_row = wc * 32 + (lq >> 1) * 8 + lr;  // + np*16
    int b_cb  = lq & 1;                        // + kk*2

    if (tid < TN) bias_s[tid] = bias[(size_t)e * DMODEL + n0 + tid];

    // loader: chunk c=tid&3; A rows tid>>2 and +64; B row tid>>2
    int c = tid & 3;
    int r0 = tid >> 2, r1 = r0 + 64;
    const __half* asrc[2]; int asz[2];
    const __half* bsrc;
    uint32_t aoff[2], boff;
    {
        int rr[2] = {r0, r1};
        #pragma unroll
        for (int j = 0; j < 2; j++) {
            int ar = row0 + rr[j];
            bool v = ar < rend;
            int srow;
            if (PHASE == 1) srow = v ? g_perm[ar] : 0;
            else            srow = v ? ar : 0;
            asrc[j] = Ax + (size_t)srow * DMODEL + c * 8;
            asz[j] = v ? 16 : 0;
            aoff[j] = swz_off(rr[j], c);
        }
        bsrc = W + (size_t)e * DMODEL * DMODEL + (size_t)(n0 + r0) * DMODEL + c * 8;
        boff = swz_off(r0, c);
    }

    float acc[2][4][4];
    #pragma unroll
    for (int mm = 0; mm < 2; mm++)
        #pragma unroll
        for (int nn = 0; nn < 4; nn++)
            #pragma unroll
            for (int j = 0; j < 4; j++) acc[mm][nn][j] = 0.f;

    // prologue: stages 0,1,2 in flight
    #pragma unroll
    for (int s = 0; s < 3; s++) {
        uint32_t aslot = ring_s + s * SLOT_A;
        uint32_t bslot = ring_s + 4 * SLOT_A + s * SLOT_BB;
        int ko = s * KSTEP;
        cpa16(aslot + aoff[0], asrc[0] + ko, asz[0]);
        cpa16(aslot + aoff[1], asrc[1] + ko, asz[1]);
        cpa16(bslot + boff, bsrc + ko, 16);
        CP_COMMIT();
    }

    // mainloop
    #pragma unroll 1
    for (int s = 0; s < NSTAGE; s++) {
        CP_WAIT2();
        __syncthreads();
        if (s + 3 < NSTAGE) {
            int sn = s + 3;
            uint32_t aslot = ring_s + (sn & 3) * SLOT_A;
            uint32_t bslot = ring_s + 4 * SLOT_A + (sn & 3) * SLOT_BB;
            int ko = sn * KSTEP;
            cpa16(aslot + aoff[0], asrc[0] + ko, asz[0]);
            cpa16(aslot + aoff[1], asrc[1] + ko, asz[1]);
            cpa16(bslot + boff, bsrc + ko, 16);
        }
        CP_COMMIT();   // commit every iter to keep wait_group accounting uniform

        uint32_t As = ring_s + (s & 3) * SLOT_A;
        uint32_t Bs = ring_s + 4 * SLOT_A + (s & 3) * SLOT_BB;
        #pragma unroll
        for (int kk = 0; kk < 2; kk++) {
            uint32_t af[2][4];
            #pragma unroll
            for (int mm = 0; mm < 2; mm++)
                ldsm4(af[mm], As + swz_off(a_row + mm * 16, a_cb + kk * 2));
            uint32_t bf[2][4];
            #pragma unroll
            for (int np = 0; np < 2; np++)
                ldsm4(bf[np], Bs + swz_off(b_row + np * 16, b_cb + kk * 2));
            #pragma unroll
            for (int np = 0; np < 2; np++) {
                mma_f16(acc[0][2 * np],     af[0], &bf[np][0]);
                mma_f16(acc[1][2 * np],     af[1], &bf[np][0]);
                mma_f16(acc[0][2 * np + 1], af[0], &bf[np][2]);
                mma_f16(acc[1][2 * np + 1], af[1], &bf[np][2]);
            }
        }
    }
    CP_WAIT0();
    __syncthreads();

    // ---- epilogue: single pass, 128 x 68 fp32 staging ----
    #pragma unroll
    for (int mm = 0; mm < 2; mm++) {
        #pragma unroll
        for (int nn = 0; nn < 4; nn++) {
            int col = wc * 32 + nn * 8 + 2 * lcol;
            int row = wr * 32 + mm * 16 + lrow;
            float b0 = bias_s[col], b1 = bias_s[col + 1];
            float v0 = acc[mm][nn][0] + b0, v1 = acc[mm][nn][1] + b1;
            float v2 = acc[mm][nn][2] + b0, v3 = acc[mm][nn][3] + b1;
            if (PHASE == 1) {
                v0 = 0.5f * v0 * (1.0f + erff(v0 * 0.70710678118654752f));
                v1 = 0.5f * v1 * (1.0f + erff(v1 * 0.70710678118654752f));
                v2 = 0.5f * v2 * (1.0f + erff(v2 * 0.70710678118654752f));
                v3 = 0.5f * v3 * (1.0f + erff(v3 * 0.70710678118654752f));
            }
            *(float2*)(stg + row * STG_STRIDE + col) = make_float2(v0, v1);
            *(float2*)(stg + (row + 8) * STG_STRIDE + col) = make_float2(v2, v3);
        }
    }
    __syncthreads();

    // writeout: 2 threads per row, 32 floats each (coalesced)
    {
        int rloc = tid >> 1, q = tid & 1;
        int gr = row0 + rloc;
        if (gr < rend) {
            const float* srow = stg + rloc * STG_STRIDE + q * 32;
            if (PHASE == 1) {
                __half* dst = g_hidden + (size_t)gr * DMODEL + n0 + q * 32;
                #pragma unroll
                for (int j = 0; j < 4; j++) {
                    float4 aa = ((const float4*)srow)[2 * j];
                    float4 bb = ((const float4*)srow)[2 * j + 1];
                    __half2 h0 = __floats2half2_rn(aa.x, aa.y);
                    __half2 h1 = __floats2half2_rn(aa.z, aa.w);
                    __half2 h2 = __floats2half2_rn(bb.x, bb.y);
                    __half2 h3 = __floats2half2_rn(bb.z, bb.w);
                    ((uint4*)dst)[j] = make_uint4(*(uint32_t*)&h0, *(uint32_t*)&h1,
                                                  *(uint32_t*)&h2, *(uint32_t*)&h3);
                }
            } else {
                float* dst = out + (size_t)g_perm[gr] * DMODEL + n0 + q * 32;
                #pragma unroll
                for (int j = 0; j < 8; j++)
                    ((float4*)dst)[j] = ((const float4*)srow)[j];
            }
        }
    }
}

// ---------------- launch -----------------------------------------------------
extern "C" void kernel_launch(void* const* d_in, const int* in_sizes, int n_in,
                              void* d_out, int out_size) {
    const float* x  = (const float*)d_in[0];
    const float* W1 = (const float*)d_in[1];
    const float* b1 = (const float*)d_in[2];
    const float* W2 = (const float*)d_in[3];
    const float* b2 = (const float*)d_in[4];
    const float* Wg = (const float*)d_in[5];
    const float* bg = (const float*)d_in[6];
    float* out = (float*)d_out;

    cudaFuncSetAttribute(mlp_mma<1>, cudaFuncAttributeMaxDynamicSharedMemorySize, SMEM_BYTES);
    cudaFuncSetAttribute(mlp_mma<2>, cudaFuncAttributeMaxDynamicSharedMemorySize, SMEM_BYTES);

    __half *xh_p, *w1h_p, *w2h_p, *hid_p;
    cudaGetSymbolAddress((void**)&xh_p, g_xh);
    cudaGetSymbolAddress((void**)&w1h_p, g_w1h);
    cudaGetSymbolAddress((void**)&w2h_p, g_w2h);
    cudaGetSymbolAddress((void**)&hid_p, g_hidden);

    int nW8 = NEXP * DMODEL * DMODEL / 8;          // 1,179,648
    cvtw_kernel<<<(2 * nW8 + 255) / 256, 256>>>(W1, W2, w1h_p, w2h_p, nW8);
    gate_kernel<<<T_TOK / 8, 256>>>(x, Wg, bg);
    scan_kernel<<<1, 1>>>();
    scatter_kernel<<<(T_TOK + 255) / 256, 256>>>();

    dim3 g(MAX_TILES, DMODEL / TN);
    mlp_mma<1><<<g, 256, SMEM_BYTES>>>(xh_p, w1h_p, b1, nullptr);
    mlp_mma<2><<<g, 256, SMEM_BYTES>>>(hid_p, w2h_p, b2, out);
}

// round 13
// speedup vs baseline: 1.9804x; 1.0861x over previous
#include <cuda_runtime.h>
#include <cuda_fp16.h>
#include <cstdint>
#include <math.h>

#define T_TOK 6304
#define DMODEL 768
#define NEXP 16
#define TM 128
#define TN 64
#define NBLK (DMODEL / TN)           // 12
#define KSTEP 32                     // halfs per stage
#define NSTAGE (DMODEL / KSTEP)      // 24
#define MAX_TILES 128
#define GATE_BLOCKS (T_TOK / 8)      // 788
#define NW8 (NEXP * DMODEL * DMODEL / 8)
#define CVT_BLOCKS (2 * NW8 / 256)   // 9216
#define PERSIST_CTAS 444             // 148 SMs x 3

#define SLOT_A 8192                  // A stage slot: 128 rows x 64 B
#define SLOT_BB 4096                 // B stage slot: 64 rows x 64 B
#define RING_OFF 2048
#define SMEM_BYTES (RING_OFF + 4 * SLOT_A + 4 * SLOT_BB)   // 51200
#define STG_STRIDE 68                // epilogue staging row stride (floats)

// ---------------- scratch (device globals; no allocations allowed) ----------
__device__ __half g_xh[T_TOK * DMODEL];
__device__ __half g_w1h[NEXP * DMODEL * DMODEL];
__device__ __half g_w2h[NEXP * DMODEL * DMODEL];
__device__ __half g_hidden[T_TOK * DMODEL];
__device__ int    g_idx[T_TOK];
__device__ int    g_counts[NEXP];     // zeroed at end of each run (GEMM kernel)
__device__ int    g_cursor2[NEXP];    // zeroed at end of each run (GEMM kernel)
__device__ int    g_off[NEXP + 1];
__device__ int    g_perm[T_TOK];
__device__ int    g_tile_e[MAX_TILES];
__device__ int    g_tile_row[MAX_TILES];
__device__ int    g_ntiles;
__device__ int    g_jobctr;           // zeroed by scatter each run
__device__ int    g_done[MAX_TILES];  // zeroed by scatter each run

// ---------------- helpers ----------------------------------------------------
__device__ __forceinline__ void ldsm4(uint32_t* r, uint32_t addr) {
    asm volatile("ldmatrix.sync.aligned.m8n8.x4.shared.b16 {%0,%1,%2,%3}, [%4];"
                 : "=r"(r[0]), "=r"(r[1]), "=r"(r[2]), "=r"(r[3]) : "r"(addr));
}
__device__ __forceinline__ void mma_f16(float* c, const uint32_t* a, const uint32_t* b) {
    asm volatile(
        "mma.sync.aligned.m16n8k16.row.col.f32.f16.f16.f32 "
        "{%0,%1,%2,%3}, {%4,%5,%6,%7}, {%8,%9}, {%0,%1,%2,%3};"
        : "+f"(c[0]), "+f"(c[1]), "+f"(c[2]), "+f"(c[3])
        : "r"(a[0]), "r"(a[1]), "r"(a[2]), "r"(a[3]), "r"(b[0]), "r"(b[1]));
}
__device__ __forceinline__ void cpa16(uint32_t dst, const void* src, int srcsize) {
    asm volatile("cp.async.cg.shared.global [%0], [%1], 16, %2;"
                 :: "r"(dst), "l"(src), "r"(srcsize) : "memory");
}
#define CP_COMMIT() asm volatile("cp.async.commit_group;" ::: "memory")
#define CP_WAIT2()  asm volatile("cp.async.wait_group 2;" ::: "memory")
#define CP_WAIT0()  asm volatile("cp.async.wait_group 0;" ::: "memory")

__device__ __forceinline__ uint32_t swz_off(int row, int c) {
    return (uint32_t)(row * 64 + ((c ^ ((row >> 1) & 3)) << 4));
}

// ---------------- prep: gate (+x->fp16) blocks || weight-convert blocks ------
__global__ void prep_kernel(const float* __restrict__ x,
                            const float* __restrict__ Wg,
                            const float* __restrict__ bg,
                            const float* __restrict__ W1,
                            const float* __restrict__ W2) {
    int tid = threadIdx.x;
    if (blockIdx.x >= GATE_BLOCKS) {
        // -------- weight convert --------
        int i = (blockIdx.x - GATE_BLOCKS) * 256 + tid;
        const float* src; __half* dst; int j;
        if (i < NW8) { src = W1; dst = g_w1h; j = i; }
        else         { src = W2; dst = g_w2h; j = i - NW8; }
        const float4* s = (const float4*)src + 2 * (size_t)j;
        float4 a = s[0], b = s[1];
        __half2 h0 = __floats2half2_rn(a.x, a.y), h1 = __floats2half2_rn(a.z, a.w);
        __half2 h2 = __floats2half2_rn(b.x, b.y), h3 = __floats2half2_rn(b.z, b.w);
        ((uint4*)dst)[j] = make_uint4(*(uint32_t*)&h0, *(uint32_t*)&h1,
                                      *(uint32_t*)&h2, *(uint32_t*)&h3);
        return;
    }
    // -------- gate --------
    __shared__ float wgs[NEXP * DMODEL];
    for (int i = tid; i < NEXP * DMODEL; i += 256) wgs[i] = Wg[i];
    __syncthreads();

    int w = tid >> 5, l = tid & 31;
    int t = blockIdx.x * 8 + w;
    {
        const float* xr = x + (size_t)t * DMODEL;
        float xv[24];
        #pragma unroll
        for (int j = 0; j < 24; j++) xv[j] = xr[l + 32 * j];
        float best = -1e30f; int bi = 0;
        #pragma unroll 1
        for (int e = 0; e < NEXP; e++) {
            float s = 0.f;
            const float* wr = wgs + e * DMODEL + l;
            #pragma unroll
            for (int j = 0; j < 24; j++) s += xv[j] * wr[32 * j];
            #pragma unroll
            for (int o = 16; o; o >>= 1) s += __shfl_xor_sync(0xffffffffu, s, o);
            s += bg[e];
            if (s > best) { best = s; bi = e; }   // strict > : first max (jnp.argmax)
        }
        if (l == 0) { g_idx[t] = bi; atomicAdd(&g_counts[bi], 1); }
    }
    size_t base = (size_t)blockIdx.x * 8 * DMODEL / 8;
    #pragma unroll
    for (int j = 0; j < 3; j++) {
        size_t idx = base + tid + 256 * j;
        const float4* s = (const float4*)x + 2 * idx;
        float4 a = s[0], b = s[1];
        __half2 h0 = __floats2half2_rn(a.x, a.y), h1 = __floats2half2_rn(a.z, a.w);
        __half2 h2 = __floats2half2_rn(b.x, b.y), h3 = __floats2half2_rn(b.z, b.w);
        ((uint4*)g_xh)[idx] = make_uint4(*(uint32_t*)&h0, *(uint32_t*)&h1,
                                         *(uint32_t*)&h2, *(uint32_t*)&h3);
    }
}

// ---------------- scatter (absorbs scan; resets GEMM-side state) -------------
__global__ void scatter_kernel() {
    __shared__ int s_off[NEXP];
    int tid = threadIdx.x;
    if (tid == 0) {
        int off = 0;
        #pragma unroll
        for (int e = 0; e < NEXP; e++) { s_off[e] = off; off += g_counts[e]; }
    }
    __syncthreads();
    int t = blockIdx.x * 256 + tid;
    if (t < T_TOK) {
        int e = g_idx[t];
        int p = s_off[e] + atomicAdd(&g_cursor2[e], 1);
        g_perm[p] = t;
    }
    if (blockIdx.x == 0) {
        if (tid == 0) {
            int off = 0, nt = 0;
            for (int e = 0; e < NEXP; e++) {
                g_off[e] = off;
                int c = g_counts[e];
                for (int r = 0; r < c; r += TM) { g_tile_e[nt] = e; g_tile_row[nt] = off + r; nt++; }
                off += c;
            }
            g_off[NEXP] = off;
            g_ntiles = nt;
            g_jobctr = 0;
        }
        if (tid < MAX_TILES) g_done[tid] = 0;
    }
}

// ---------------- fused persistent grouped GEMM ------------------------------
// jobs (tile-major): [0, 12*nt)   phase1: hidden = fp16(GELU(xh@W1^T + b1))
//                    [12nt, 24nt) phase2: out    = hidden@W2^T + b2
__global__ void __launch_bounds__(256, 3)
mlp_fused(const float* __restrict__ b1, const float* __restrict__ b2,
          float* __restrict__ out)
{
    extern __shared__ char sm[];
    float* bias_s = (float*)sm;
    int* s_jid = (int*)(sm + 1024);
    char* ring = sm + RING_OFF;
    uint32_t ring_s = (uint32_t)__cvta_generic_to_shared(ring);
    float* stg = (float*)ring;

    int tid = threadIdx.x;
    int wid = tid >> 5, lane = tid & 31;
    int wr = wid & 3, wc = wid >> 2;
    int lrow = lane >> 2, lcol = lane & 3;
    int lq = lane >> 3, lr = lane & 7;
    int a_row = wr * 32 + (lq & 1) * 8 + lr;
    int a_cb  = lq >> 1;
    int b_row = wc * 32 + (lq >> 1) * 8 + lr;
    int b_cb  = lq & 1;
    int c = tid & 3;
    int r0 = tid >> 2, r1 = r0 + 64;

    // reset inter-run state (nothing in this kernel reads these)
    if (blockIdx.x == 0 && tid < NEXP) { g_counts[tid] = 0; g_cursor2[tid] = 0; }

    int ntiles = g_ntiles;
    int per = NBLK * ntiles;
    int total = 2 * per;

    for (;;) {
        if (tid == 0) *s_jid = atomicAdd(&g_jobctr, 1);
        __syncthreads();
        int jid = *s_jid;
        __syncthreads();
        if (jid >= total) break;

        int phase = (jid < per) ? 1 : 2;
        int jj = (phase == 1) ? jid : jid - per;
        int tile = jj / NBLK, nb = jj - tile * NBLK;
        int e = g_tile_e[tile];
        int row0 = g_tile_row[tile];
        int rend = g_off[e + 1];
        int n0 = nb * TN;

        // phase2: wait for this tile's 12 hidden slabs
        if (phase == 2) {
            if (tid == 0) {
                while (atomicAdd(&g_done[tile], 0) < NBLK) __nanosleep(64);
            }
            __syncthreads();
            __threadfence();   // acquire: hidden writes now visible
        }

        const float* bias = (phase == 1) ? b1 : b2;
        if (tid < TN) bias_s[tid] = bias[(size_t)e * DMODEL + n0 + tid];

        // loader sources
        const __half* Ax = (phase == 1) ? g_xh : g_hidden;
        const __half* W  = (phase == 1) ? g_w1h : g_w2h;
        const __half* asrc[2]; int asz[2];
        const __half* bsrc;
        uint32_t aoff[2], boff;
        {
            int rr[2] = {r0, r1};
            #pragma unroll
            for (int j = 0; j < 2; j++) {
                int ar = row0 + rr[j];
                bool v = ar < rend;
                int srow;
                if (phase == 1) srow = v ? g_perm[ar] : 0;
                else            srow = v ? ar : 0;
                asrc[j] = Ax + (size_t)srow * DMODEL + c * 8;
                asz[j] = v ? 16 : 0;
                aoff[j] = swz_off(rr[j], c);
            }
            bsrc = W + (size_t)e * DMODEL * DMODEL + (size_t)(n0 + r0) * DMODEL + c * 8;
            boff = swz_off(r0, c);
        }

        float acc[2][4][4];
        #pragma unroll
        for (int mm = 0; mm < 2; mm++)
            #pragma unroll
            for (int nn = 0; nn < 4; nn++)
                #pragma unroll
                for (int j = 0; j < 4; j++) acc[mm][nn][j] = 0.f;

        // prologue: stages 0,1,2 in flight
        #pragma unroll
        for (int s = 0; s < 3; s++) {
            uint32_t aslot = ring_s + s * SLOT_A;
            uint32_t bslot = ring_s + 4 * SLOT_A + s * SLOT_BB;
            int ko = s * KSTEP;
            cpa16(aslot + aoff[0], asrc[0] + ko, asz[0]);
            cpa16(aslot + aoff[1], asrc[1] + ko, asz[1]);
            cpa16(bslot + boff, bsrc + ko, 16);
            CP_COMMIT();
        }

        // mainloop
        #pragma unroll 1
        for (int s = 0; s < NSTAGE; s++) {
            CP_WAIT2();
            __syncthreads();
            if (s + 3 < NSTAGE) {
                int sn = s + 3;
                uint32_t aslot = ring_s + (sn & 3) * SLOT_A;
                uint32_t bslot = ring_s + 4 * SLOT_A + (sn & 3) * SLOT_BB;
                int ko = sn * KSTEP;
                cpa16(aslot + aoff[0], asrc[0] + ko, asz[0]);
                cpa16(aslot + aoff[1], asrc[1] + ko, asz[1]);
                cpa16(bslot + boff, bsrc + ko, 16);
            }
            CP_COMMIT();

            uint32_t As = ring_s + (s & 3) * SLOT_A;
            uint32_t Bs = ring_s + 4 * SLOT_A + (s & 3) * SLOT_BB;
            #pragma unroll
            for (int kk = 0; kk < 2; kk++) {
                uint32_t af[2][4];
                #pragma unroll
                for (int mm = 0; mm < 2; mm++)
                    ldsm4(af[mm], As + swz_off(a_row + mm * 16, a_cb + kk * 2));
                uint32_t bf[2][4];
                #pragma unroll
                for (int np = 0; np < 2; np++)
                    ldsm4(bf[np], Bs + swz_off(b_row + np * 16, b_cb + kk * 2));
                #pragma unroll
                for (int np = 0; np < 2; np++) {
                    mma_f16(acc[0][2 * np],     af[0], &bf[np][0]);
                    mma_f16(acc[1][2 * np],     af[1], &bf[np][0]);
                    mma_f16(acc[0][2 * np + 1], af[0], &bf[np][2]);
                    mma_f16(acc[1][2 * np + 1], af[1], &bf[np][2]);
                }
            }
        }
        CP_WAIT0();
        __syncthreads();

        // epilogue: bias (+GELU) -> staging -> coalesced writeout
        #pragma unroll
        for (int mm = 0; mm < 2; mm++) {
            #pragma unroll
            for (int nn = 0; nn < 4; nn++) {
                int col = wc * 32 + nn * 8 + 2 * lcol;
                int row = wr * 32 + mm * 16 + lrow;
                float bb0 = bias_s[col], bb1 = bias_s[col + 1];
                float v0 = acc[mm][nn][0] + bb0, v1 = acc[mm][nn][1] + bb1;
                float v2 = acc[mm][nn][2] + bb0, v3 = acc[mm][nn][3] + bb1;
                if (phase == 1) {
                    v0 = 0.5f * v0 * (1.0f + erff(v0 * 0.70710678118654752f));
                    v1 = 0.5f * v1 * (1.0f + erff(v1 * 0.70710678118654752f));
                    v2 = 0.5f * v2 * (1.0f + erff(v2 * 0.70710678118654752f));
                    v3 = 0.5f * v3 * (1.0f + erff(v3 * 0.70710678118654752f));
                }
                *(float2*)(stg + row * STG_STRIDE + col) = make_float2(v0, v1);
                *(float2*)(stg + (row + 8) * STG_STRIDE + col) = make_float2(v2, v3);
            }
        }
        __syncthreads();
        {
            int rloc = tid >> 1, q = tid & 1;
            int gr = row0 + rloc;
            if (gr < rend) {
                const float* srow = stg + rloc * STG_STRIDE + q * 32;
                if (phase == 1) {
                    __half* dst = g_hidden + (size_t)gr * DMODEL + n0 + q * 32;
                    #pragma unroll
                    for (int j = 0; j < 4; j++) {
                        float4 aa = ((const float4*)srow)[2 * j];
                        float4 bb = ((const float4*)srow)[2 * j + 1];
                        __half2 h0 = __floats2half2_rn(aa.x, aa.y);
                        __half2 h1 = __floats2half2_rn(aa.z, aa.w);
                        __half2 h2 = __floats2half2_rn(bb.x, bb.y);
                        __half2 h3 = __floats2half2_rn(bb.z, bb.w);
                        ((uint4*)dst)[j] = make_uint4(*(uint32_t*)&h0, *(uint32_t*)&h1,
                                                      *(uint32_t*)&h2, *(uint32_t*)&h3);
                    }
                } else {
                    float* dst = out + (size_t)g_perm[gr] * DMODEL + n0 + q * 32;
                    #pragma unroll
                    for (int j = 0; j < 8; j++)
                        ((float4*)dst)[j] = ((const float4*)srow)[j];
                }
            }
        }
        // release: signal hidden slab complete
        if (phase == 1) {
            __threadfence();
            __syncthreads();
            if (tid == 0) atomicAdd(&g_done[tile], 1);
        }
        __syncthreads();   // staging/bias reuse safe for next job
    }
}

// ---------------- launch -----------------------------------------------------
extern "C" void kernel_launch(void* const* d_in, const int* in_sizes, int n_in,
                              void* d_out, int out_size) {
    const float* x  = (const float*)d_in[0];
    const float* W1 = (const float*)d_in[1];
    const float* b1 = (const float*)d_in[2];
    const float* W2 = (const float*)d_in[3];
    const float* b2 = (const float*)d_in[4];
    const float* Wg = (const float*)d_in[5];
    const float* bg = (const float*)d_in[6];
    float* out = (float*)d_out;

    cudaFuncSetAttribute(mlp_fused, cudaFuncAttributeMaxDynamicSharedMemorySize, SMEM_BYTES);

    prep_kernel<<<GATE_BLOCKS + CVT_BLOCKS, 256>>>(x, Wg, bg, W1, W2);
    scatter_kernel<<<(T_TOK + 255) / 256, 256>>>();
    mlp_fused<<<PERSIST_CTAS, 256, SMEM_BYTES>>>(b1, b2, out);
}